// round 6
// baseline (speedup 1.0000x reference)
#include <cuda_runtime.h>

#define D 64
#define KC 400
#define KPAD 512
#define MTILE 128
#define NTILE 128
#define NCHUNKS 4
#define TPB 256
#define TSTRIDE 132   // padded fast-dim stride (floats) for [d][.] tiles, 16B aligned

// smem byte offsets (dynamic)
#define OFF_XS   0
#define OFF_ES   33792              // 64*132*4
#define OFF_N2C  67584              // + 64*132*4
#define OFF_RWIN 68096              // + 128*4
#define SMEM_BYTES 68608
// reduction overlays es after last chunk
#define OFF_SB   OFF_ES
#define OFF_SI   (OFF_ES + 8704)    // 128*17*4

__device__ __forceinline__ void fma2(unsigned long long &acc, unsigned long long a,
                                     unsigned long long b) {
    asm("fma.rn.f32x2 %0, %1, %2, %0;" : "+l"(acc) : "l"(a), "l"(b));
}
__device__ __forceinline__ void unpack2(unsigned long long v, float &lo, float &hi) {
    asm("mov.b64 {%0, %1}, %2;" : "=f"(lo), "=f"(hi) : "l"(v));
}
__device__ __forceinline__ unsigned long long pack2(float lo, float hi) {
    unsigned long long r;
    asm("mov.b64 %0, {%1, %2};" : "=l"(r) : "f"(lo), "f"(hi));
    return r;
}

__global__ void __launch_bounds__(TPB, 2)
vq_tiled_kernel(const float* __restrict__ x, const float* __restrict__ emb,
                float* __restrict__ out, int nrows) {
    extern __shared__ char sm[];
    float* xs   = (float*)(sm + OFF_XS);    // [64][TSTRIDE] x-tile transposed
    float* es   = (float*)(sm + OFF_ES);    // [64][TSTRIDE] e-chunk transposed
    float* n2c  = (float*)(sm + OFF_N2C);   // [128] -0.5*||e||^2 for current chunk
    int*   rwin = (int*)(sm + OFF_RWIN);    // [128] winning code per row

    const int tid = threadIdx.x;
    const int tx = tid & 15;     // code group
    const int ty = tid >> 4;     // row group
    const int row0 = blockIdx.x * MTILE;

    // ---- stage x tile, transposed: xs[d][row] ----
    {
        const float4* xg = (const float4*)(x + (size_t)row0 * D);
        for (int i = tid; i < MTILE * (D / 4); i += TPB) {
            int row = i >> 4, db = i & 15;
            float4 v = xg[row * (D / 4) + db];
            xs[(db * 4 + 0) * TSTRIDE + row] = v.x;
            xs[(db * 4 + 1) * TSTRIDE + row] = v.y;
            xs[(db * 4 + 2) * TSTRIDE + row] = v.z;
            xs[(db * 4 + 3) * TSTRIDE + row] = v.w;
        }
    }

    unsigned long long acc[32];            // [m][np] packed pair accumulators
    float bst[8];
    int   bidx[8];
    #pragma unroll
    for (int m = 0; m < 8; m++) { bst[m] = -3.4e38f; bidx[m] = 0; }

    const float4* eg = (const float4*)emb;

    for (int c = 0; c < NCHUNKS; c++) {
        const int g0 = c * NTILE;
        __syncthreads();   // previous chunk's readers done (also covers xs staging on c=0)

        // ---- stage e chunk, transposed: es[d][code]; zero for pad codes ----
        for (int i = tid; i < NTILE * (D / 4); i += TPB) {
            int code = i >> 4, db = i & 15;
            float4 v = make_float4(0.f, 0.f, 0.f, 0.f);
            if (g0 + code < KC) v = eg[(size_t)(g0 + code) * (D / 4) + db];
            es[(db * 4 + 0) * TSTRIDE + code] = v.x;
            es[(db * 4 + 1) * TSTRIDE + code] = v.y;
            es[(db * 4 + 2) * TSTRIDE + code] = v.z;
            es[(db * 4 + 3) * TSTRIDE + code] = v.w;
        }
        __syncthreads();

        // ---- norms for this chunk (from staged tile; conflict-free strided LDS) ----
        if (tid < NTILE) {
            float s = -3.4e38f;
            if (g0 + tid < KC) {
                s = 0.f;
                #pragma unroll 16
                for (int d = 0; d < D; d++) {
                    float e = es[d * TSTRIDE + tid];
                    s = fmaf(e, e, s);
                }
                s = -0.5f * s;
            }
            n2c[tid] = s;
        }
        __syncthreads();

        #pragma unroll
        for (int i = 0; i < 32; i++) acc[i] = 0ull;

        // ---- main MMA loop over d ----
        #pragma unroll 4
        for (int d = 0; d < D; d++) {
            const float* xr = xs + d * TSTRIDE + ty * 8;
            const float* er = es + d * TSTRIDE + tx * 8;
            float4 xa = *(const float4*)xr;
            float4 xb = *(const float4*)(xr + 4);
            ulonglong2 ea = *(const ulonglong2*)er;       // e pairs (n0,n1),(n2,n3)
            ulonglong2 eb = *(const ulonglong2*)(er + 4); // (n4,n5),(n6,n7)
            unsigned long long ep0 = ea.x, ep1 = ea.y, ep2 = eb.x, ep3 = eb.y;
            float xm[8] = {xa.x, xa.y, xa.z, xa.w, xb.x, xb.y, xb.z, xb.w};
            #pragma unroll
            for (int m = 0; m < 8; m++) {
                unsigned long long xp = pack2(xm[m], xm[m]);
                fma2(acc[m * 4 + 0], xp, ep0);
                fma2(acc[m * 4 + 1], xp, ep1);
                fma2(acc[m * 4 + 2], xp, ep2);
                fma2(acc[m * 4 + 3], xp, ep3);
            }
        }

        // ---- chunk epilogue: add norms, update per-row best ----
        // strict > with ascending global index => jnp.argmin first-min tie-break
        #pragma unroll
        for (int m = 0; m < 8; m++) {
            #pragma unroll
            for (int np = 0; np < 4; np++) {
                float lo, hi;
                unpack2(acc[m * 4 + np], lo, hi);
                int n = tx * 8 + np * 2;
                float s0 = lo + n2c[n];
                float s1 = hi + n2c[n + 1];
                if (s0 > bst[m]) { bst[m] = s0; bidx[m] = g0 + n; }
                if (s1 > bst[m]) { bst[m] = s1; bidx[m] = g0 + n + 1; }
            }
        }
    }

    // ---- cross-thread reduction over tx (16 candidates per row) ----
    __syncthreads();
    float* sb = (float*)(sm + OFF_SB);   // [128][17]
    int*   si = (int*)(sm + OFF_SI);     // [128][17]
    #pragma unroll
    for (int m = 0; m < 8; m++) {
        int row = ty * 8 + m;
        sb[row * 17 + tx] = bst[m];
        si[row * 17 + tx] = bidx[m];
    }
    __syncthreads();
    if (tid < MTILE) {
        float b = -3.4e38f;
        int bi = 0;
        #pragma unroll
        for (int t = 0; t < 16; t++) {
            float s = sb[tid * 17 + t];
            int   i = si[tid * 17 + t];
            if (s > b || (s == b && i < bi)) { b = s; bi = i; }
        }
        rwin[tid] = bi;
    }
    __syncthreads();

    // ---- gather winning codes (L2-hot), write out ----
    float4* og = (float4*)(out + (size_t)row0 * D);
    for (int i = tid; i < MTILE * (D / 4); i += TPB) {
        int r = i >> 4, q = i & 15;
        og[r * (D / 4) + q] = eg[(size_t)rwin[r] * (D / 4) + q];
    }
}

extern "C" void kernel_launch(void* const* d_in, const int* in_sizes, int n_in,
                              void* d_out, int out_size) {
    const float* x   = (const float*)d_in[0];
    const float* emb = (const float*)d_in[1];
    float* out = (float*)d_out;

    int nrows = in_sizes[0] / D;   // 262144 (divisible by MTILE)

    cudaFuncSetAttribute(vq_tiled_kernel,
                         cudaFuncAttributeMaxDynamicSharedMemorySize, SMEM_BYTES);

    int blocks = nrows / MTILE;    // 2048
    vq_tiled_kernel<<<blocks, TPB, SMEM_BYTES>>>(x, emb, out, nrows);
}

// round 7
// speedup vs baseline: 1.2345x; 1.2345x over previous
#include <cuda_runtime.h>

#define D 64
#define KC 400
#define MTILE 128
#define NTILE 128
#define TPB 256
#define TS 132            // padded stride (floats) for [d][.] tiles, 16B aligned
#define NFULL 3           // 3 full chunks of 128 codes
#define KTAIL 16          // tail codes 384..399

// smem byte offsets
#define OFF_XS 0                  // float[64*TS]
#define OFF_ES 33792              // float[64*TS]
#define OFF_N2 67584              // float[128]
#define OFF_RW 68096              // int[128]
#define SMEM_BYTES 68608
// reduction overlays es after all compute
#define OFF_SB OFF_ES             // float[128*19]
#define OFF_SI (OFF_ES + 9728)    // int[128*19]

__device__ __forceinline__ void fma2(unsigned long long &acc, unsigned long long a,
                                     unsigned long long b) {
    asm("fma.rn.f32x2 %0, %1, %2, %0;" : "+l"(acc) : "l"(a), "l"(b));
}
__device__ __forceinline__ void unpack2(unsigned long long v, float &lo, float &hi) {
    asm("mov.b64 {%0, %1}, %2;" : "=f"(lo), "=f"(hi) : "l"(v));
}
__device__ __forceinline__ unsigned long long pack2(float lo, float hi) {
    unsigned long long r;
    asm("mov.b64 %0, {%1, %2};" : "=l"(r) : "f"(lo), "f"(hi));
    return r;
}

__global__ void __launch_bounds__(TPB, 2)
vq_tiled_kernel(const float* __restrict__ x, const float* __restrict__ emb,
                float* __restrict__ out, int nrows) {
    extern __shared__ char sm[];
    float* xs  = (float*)(sm + OFF_XS);
    float* es  = (float*)(sm + OFF_ES);
    float* n2c = (float*)(sm + OFF_N2);
    int*   rw  = (int*)(sm + OFF_RW);

    const int tid = threadIdx.x;
    const int tx = tid & 15;        // code group (8 codes)
    const int ty = tid >> 4;        // row group (8 rows)
    const int row0 = blockIdx.x * MTILE;

    const float4* xg = (const float4*)(x + (size_t)row0 * D);
    const float4* eg = (const float4*)emb;

    // ---- stage x transposed, conflict-free STS (row-inner mapping) ----
    for (int i = tid; i < MTILE * (D / 4); i += TPB) {
        int row = i & 127, db = i >> 7;
        float4 v = make_float4(0.f, 0.f, 0.f, 0.f);
        if (row0 + row < nrows) v = xg[row * 16 + db];
        xs[(4 * db + 0) * TS + row] = v.x;   // bank = const + row: conflict-free
        xs[(4 * db + 1) * TS + row] = v.y;
        xs[(4 * db + 2) * TS + row] = v.z;
        xs[(4 * db + 3) * TS + row] = v.w;
    }

    unsigned long long acc[32];
    float bst[8];
    int   bidx[8];
    #pragma unroll
    for (int m = 0; m < 8; m++) { bst[m] = -3.4e38f; bidx[m] = 0; }

    for (int c = 0; c < NFULL; c++) {
        const int g0 = c * NTILE;
        __syncthreads();                         // prev chunk readers done (+x stage on c=0)

        // ---- stage e chunk transposed, conflict-free (code-inner mapping) ----
        for (int i = tid; i < NTILE * (D / 4); i += TPB) {
            int code = i & 127, db = i >> 7;
            float4 v = eg[(size_t)(g0 + code) * 16 + db];
            es[(4 * db + 0) * TS + code] = v.x;
            es[(4 * db + 1) * TS + code] = v.y;
            es[(4 * db + 2) * TS + code] = v.z;
            es[(4 * db + 3) * TS + code] = v.w;
        }
        __syncthreads();

        // ---- -0.5*||e||^2 per code (strided LDS, conflict-free) ----
        if (tid < NTILE) {
            float s = 0.f;
            #pragma unroll 16
            for (int d = 0; d < D; d++) {
                float e = es[d * TS + tid];
                s = fmaf(e, e, s);
            }
            n2c[tid] = -0.5f * s;
        }
        __syncthreads();

        // ---- init accumulators with folded norms (pairs as u64) ----
        #pragma unroll
        for (int np = 0; np < 4; np++) {
            unsigned long long n2 = *(const unsigned long long*)(n2c + tx * 8 + np * 2);
            #pragma unroll
            for (int m = 0; m < 8; m++) acc[m * 4 + np] = n2;
        }

        // ---- MMA over d ----
        #pragma unroll 8
        for (int d = 0; d < D; d++) {
            const float* xr = xs + d * TS + ty * 8;
            const float* er = es + d * TS + tx * 8;
            float4 xa = *(const float4*)xr;
            float4 xb = *(const float4*)(xr + 4);
            ulonglong2 ea = *(const ulonglong2*)er;
            ulonglong2 eb = *(const ulonglong2*)(er + 4);
            unsigned long long ep0 = ea.x, ep1 = ea.y, ep2 = eb.x, ep3 = eb.y;
            float xm[8] = {xa.x, xa.y, xa.z, xa.w, xb.x, xb.y, xb.z, xb.w};
            #pragma unroll
            for (int m = 0; m < 8; m++) {
                unsigned long long xp = pack2(xm[m], xm[m]);
                fma2(acc[m * 4 + 0], xp, ep0);
                fma2(acc[m * 4 + 1], xp, ep1);
                fma2(acc[m * 4 + 2], xp, ep2);
                fma2(acc[m * 4 + 3], xp, ep3);
            }
        }

        // ---- chunk epilogue: scores are in accs; strict > => first-min tie-break ----
        #pragma unroll
        for (int m = 0; m < 8; m++) {
            #pragma unroll
            for (int np = 0; np < 4; np++) {
                float lo, hi;
                unpack2(acc[m * 4 + np], lo, hi);
                int n = g0 + tx * 8 + np * 2;
                if (lo > bst[m]) { bst[m] = lo; bidx[m] = n; }
                if (hi > bst[m]) { bst[m] = hi; bidx[m] = n + 1; }
            }
        }
    }

    // ================= tail: codes 384..399 =================
    __syncthreads();
    for (int i = tid; i < KTAIL * (D / 4); i += TPB) {   // 256 items: 1 iter
        int code = i & 15, db = i >> 4;
        float4 v = eg[(size_t)(NFULL * NTILE + code) * 16 + db];
        es[(4 * db + 0) * TS + code] = v.x;
        es[(4 * db + 1) * TS + code] = v.y;
        es[(4 * db + 2) * TS + code] = v.z;
        es[(4 * db + 3) * TS + code] = v.w;
    }
    __syncthreads();
    if (tid < KTAIL) {
        float s = 0.f;
        #pragma unroll 16
        for (int d = 0; d < D; d++) {
            float e = es[d * TS + tid];
            s = fmaf(e, e, s);
        }
        n2c[tid] = -0.5f * s;
    }
    __syncthreads();

    float tb;
    int   ti;
    {
        const int tx2 = tid & 1;          // 2 code-groups of 8
        const int trow = tid >> 1;        // 1 row per thread
        unsigned long long a2[4];
        #pragma unroll
        for (int np = 0; np < 4; np++)
            a2[np] = *(const unsigned long long*)(n2c + tx2 * 8 + np * 2);
        #pragma unroll 8
        for (int d = 0; d < D; d++) {
            float xv = xs[d * TS + trow];
            unsigned long long xp = pack2(xv, xv);
            const ulonglong2* er = (const ulonglong2*)(es + d * TS + tx2 * 8);
            ulonglong2 ea = er[0], eb = er[1];
            fma2(a2[0], xp, ea.x);
            fma2(a2[1], xp, ea.y);
            fma2(a2[2], xp, eb.x);
            fma2(a2[3], xp, eb.y);
        }
        tb = -3.4e38f; ti = 0;
        #pragma unroll
        for (int np = 0; np < 4; np++) {
            float lo, hi;
            unpack2(a2[np], lo, hi);
            int n = NFULL * NTILE + tx2 * 8 + np * 2;
            if (lo > tb) { tb = lo; ti = n; }
            if (hi > tb) { tb = hi; ti = n + 1; }
        }
    }

    // ---- cross-thread reduction: 18 candidates per row ----
    __syncthreads();                       // all es readers done; overlay sb/si
    float* sb = (float*)(sm + OFF_SB);     // [128][19]
    int*   si = (int*)(sm + OFF_SI);       // [128][19]
    #pragma unroll
    for (int m = 0; m < 8; m++) {
        int row = ty * 8 + m;
        sb[row * 19 + tx] = bst[m];
        si[row * 19 + tx] = bidx[m];
    }
    {
        int row = tid >> 1, slot = 16 + (tid & 1);
        sb[row * 19 + slot] = tb;
        si[row * 19 + slot] = ti;
    }
    __syncthreads();
    if (tid < MTILE) {
        float b = -3.4e38f;
        int bi = 0;
        #pragma unroll
        for (int t = 0; t < 18; t++) {
            float s = sb[tid * 19 + t];
            int   i = si[tid * 19 + t];
            if (s > b || (s == b && i < bi)) { b = s; bi = i; }
        }
        rw[tid] = bi;
    }
    __syncthreads();

    // ---- gather winning codes (L2-hot), write out ----
    float4* og = (float4*)(out + (size_t)row0 * D);
    for (int i = tid; i < MTILE * (D / 4); i += TPB) {
        int r = i >> 4, q = i & 15;
        if (row0 + r < nrows) og[r * 16 + q] = eg[(size_t)rw[r] * 16 + q];
    }
}

extern "C" void kernel_launch(void* const* d_in, const int* in_sizes, int n_in,
                              void* d_out, int out_size) {
    const float* x   = (const float*)d_in[0];
    const float* emb = (const float*)d_in[1];
    float* out = (float*)d_out;

    int nrows = in_sizes[0] / D;   // 262144

    cudaFuncSetAttribute(vq_tiled_kernel,
                         cudaFuncAttributeMaxDynamicSharedMemorySize, SMEM_BYTES);

    int blocks = (nrows + MTILE - 1) / MTILE;   // 2048
    vq_tiled_kernel<<<blocks, TPB, SMEM_BYTES>>>(x, emb, out, nrows);
}